// round 13
// baseline (speedup 1.0000x reference)
#include <cuda_runtime.h>
#include <cstdint>

#define Bz 8
#define Sq 1024
#define Ed 768
#define Hh 12
#define Dd 64
#define N3 2304
#define TOPK 409
#define QT 32
#define KTK 64     // K/V rows per attn tile (two K planes fit same smem)
#define KVP 72     // K/V smem row stride
#define QSP 68
#define SCP 1028

#define ASTR 20
#define BSTR 136

// ---- scratch (allocation-free rule: __device__ globals) ----
__device__ float g_Q [Bz*Hh*Sq*Dd];
__device__ float g_Kh[Bz*Hh*Sq*Dd];   // K tf32-hi plane
__device__ float g_Kl[Bz*Hh*Sq*Dd];   // K tf32-lo plane
__device__ float g_V [Bz*Hh*Sq*Dd];   // V pre-rounded to tf32
__device__ float g_AO[Bz*Sq*Ed];      // attn out [b,s,h,d]

// ---- cp.async helpers ----
__device__ __forceinline__ void cp16(void* smem_dst, const void* gmem_src) {
    unsigned s = (unsigned)__cvta_generic_to_shared(smem_dst);
    asm volatile("cp.async.cg.shared.global [%0], [%1], 16;" :: "r"(s), "l"(gmem_src));
}
__device__ __forceinline__ void cp_commit() { asm volatile("cp.async.commit_group;"); }
template<int N>
__device__ __forceinline__ void cp_wait() { asm volatile("cp.async.wait_group %0;" :: "n"(N)); }

// ---- tf32 helpers ----
__device__ __forceinline__ uint32_t f2tf(float x) {
    uint32_t r; asm("cvt.rna.tf32.f32 %0, %1;" : "=r"(r) : "f"(x)); return r;
}
__device__ __forceinline__ void split_tf32(float x, uint32_t& hi, uint32_t& lo) {
    uint32_t h;
    asm("cvt.rna.tf32.f32 %0, %1;" : "=r"(h) : "f"(x));
    float l = x - __uint_as_float(h);
    uint32_t lw;
    asm("cvt.rna.tf32.f32 %0, %1;" : "=r"(lw) : "f"(l));
    hi = h; lo = lw;
}
__device__ __forceinline__ void mma_tf32(float4& d, const uint32_t a[4], const uint32_t b[2]) {
    asm volatile("mma.sync.aligned.m16n8k8.row.col.f32.tf32.tf32.f32 "
                 "{%0,%1,%2,%3}, {%4,%5,%6,%7}, {%8,%9}, {%0,%1,%2,%3};"
                 : "+f"(d.x), "+f"(d.y), "+f"(d.z), "+f"(d.w)
                 : "r"(a[0]), "r"(a[1]), "r"(a[2]), "r"(a[3]), "r"(b[0]), "r"(b[1]));
}

// ---- 32x32 bit-matrix transpose (Hacker's Delight 7-7) ----
template<int J>
__device__ __forceinline__ void tstage(unsigned a[32], unsigned m) {
    #pragma unroll
    for (int g = 0; g < 16; g++) {
        const int k = ((g & ~(J - 1)) << 1) | (g & (J - 1));
        unsigned t = (a[k] ^ (a[k + J] >> J)) & m;
        a[k]     ^= t;
        a[k + J] ^= (t << J);
    }
}
__device__ __forceinline__ void bit_transpose32(unsigned a[32]) {
    tstage<16>(a, 0x0000FFFFu);
    tstage<8> (a, 0x00FF00FFu);
    tstage<4> (a, 0x0F0F0F0Fu);
    tstage<2> (a, 0x33333333u);
    tstage<1> (a, 0x55555555u);
}

// ============================================================
// 3xTF32 GEMM (R11 version — in-loop split). Epilogue scatter
// writes Q plain, K pre-split hi/lo, V pre-rounded tf32.
// ============================================================
template<int NDIM, bool SCATTER>
__global__ __launch_bounds__(256, 2) void gemm_tf32(const float* __restrict__ A_in,
                                                    const float* __restrict__ W,
                                                    const float* __restrict__ bias,
                                                    float* __restrict__ out) {
    const float* A = SCATTER ? A_in : (const float*)g_AO;   // device-side symbol!

    __shared__ float As[2][128*ASTR];
    __shared__ float Bs[2][16*BSTR];

    const int t    = threadIdx.x;
    const int warp = t >> 5, lane = t & 31;
    const int gid  = lane >> 2, tig = lane & 3;
    const int m0   = blockIdx.y * 128, n0 = blockIdx.x * 128;
    const int wm   = (warp >> 2) * 64;
    const int wn   = (warp & 3) * 32;

    auto issue = [&](int buf, int kt) {
        #pragma unroll
        for (int i = 0; i < 2; i++) {
            int f = t + 256*i;
            int m = f >> 2, kc = (f & 3) << 2;
            cp16(&As[buf][m*ASTR + kc], &A[(size_t)(m0 + m)*Ed + kt*16 + kc]);
        }
        #pragma unroll
        for (int i = 0; i < 2; i++) {
            int f = t + 256*i;
            int kr = f >> 5, nc = (f & 31) << 2;
            cp16(&Bs[buf][kr*BSTR + nc], &W[(size_t)(kt*16 + kr)*NDIM + n0 + nc]);
        }
        cp_commit();
    };

    float4 acc[4][4];
    #pragma unroll
    for (int i = 0; i < 4; i++)
        #pragma unroll
        for (int j = 0; j < 4; j++) acc[i][j] = make_float4(0.f, 0.f, 0.f, 0.f);

    issue(0, 0);
    const int NT = Ed / 16;
    for (int kt = 0; kt < NT; kt++) {
        if (kt + 1 < NT) { issue((kt + 1) & 1, kt + 1); cp_wait<1>(); }
        else             { cp_wait<0>(); }
        __syncthreads();
        const float* as = As[kt & 1];
        const float* bs = Bs[kt & 1];
        #pragma unroll
        for (int ko = 0; ko < 16; ko += 8) {
            uint32_t Bhi[4][2], Blo[4][2];
            #pragma unroll
            for (int j = 0; j < 4; j++) {
                const int nc = wn + 8*j + gid;
                split_tf32(bs[(ko + tig    )*BSTR + nc], Bhi[j][0], Blo[j][0]);
                split_tf32(bs[(ko + tig + 4)*BSTR + nc], Bhi[j][1], Blo[j][1]);
            }
            #pragma unroll
            for (int i = 0; i < 4; i++) {
                const int r0 = wm + 16*i + gid;
                uint32_t Ahi[4], Alo[4];
                split_tf32(as[ r0     *ASTR + ko + tig    ], Ahi[0], Alo[0]);
                split_tf32(as[(r0 + 8)*ASTR + ko + tig    ], Ahi[1], Alo[1]);
                split_tf32(as[ r0     *ASTR + ko + tig + 4], Ahi[2], Alo[2]);
                split_tf32(as[(r0 + 8)*ASTR + ko + tig + 4], Ahi[3], Alo[3]);
                #pragma unroll
                for (int j = 0; j < 4; j++) {
                    mma_tf32(acc[i][j], Alo, Bhi[j]);
                    mma_tf32(acc[i][j], Ahi, Blo[j]);
                    mma_tf32(acc[i][j], Ahi, Bhi[j]);
                }
            }
        }
        __syncthreads();
    }

    #pragma unroll
    for (int i = 0; i < 4; i++) {
        const int ma = m0 + wm + 16*i + gid;
        const int mb = ma + 8;
        #pragma unroll
        for (int j = 0; j < 4; j++) {
            const int nb = n0 + wn + 8*j + 2*tig;
            const float2 bv = *(const float2*)&bias[nb];
            float2 va = make_float2(acc[i][j].x + bv.x, acc[i][j].y + bv.y);
            float2 vb = make_float2(acc[i][j].z + bv.x, acc[i][j].w + bv.y);
            if (SCATTER) {
                const int which = nb / Ed;
                const int hh    = (nb % Ed) >> 6;
                const int d0    = nb & 63;
                const int ba = ma >> 10, sa = ma & 1023;
                const int bbq = mb >> 10, sb = mb & 1023;
                const size_t ia = (size_t)((ba*Hh + hh)*Sq + sa)*Dd + d0;
                const size_t ib = (size_t)((bbq*Hh + hh)*Sq + sb)*Dd + d0;
                if (which == 0) {
                    *(float2*)&g_Q[ia] = va;
                    *(float2*)&g_Q[ib] = vb;
                } else if (which == 1) {
                    uint32_t h, l;
                    float2 ha, la, hb, lb;
                    split_tf32(va.x, h, l); ha.x = __uint_as_float(h); la.x = __uint_as_float(l);
                    split_tf32(va.y, h, l); ha.y = __uint_as_float(h); la.y = __uint_as_float(l);
                    split_tf32(vb.x, h, l); hb.x = __uint_as_float(h); lb.x = __uint_as_float(l);
                    split_tf32(vb.y, h, l); hb.y = __uint_as_float(h); lb.y = __uint_as_float(l);
                    *(float2*)&g_Kh[ia] = ha; *(float2*)&g_Kl[ia] = la;
                    *(float2*)&g_Kh[ib] = hb; *(float2*)&g_Kl[ib] = lb;
                } else {
                    float2 ta, tb;
                    ta.x = __uint_as_float(f2tf(va.x)); ta.y = __uint_as_float(f2tf(va.y));
                    tb.x = __uint_as_float(f2tf(vb.x)); tb.y = __uint_as_float(f2tf(vb.y));
                    *(float2*)&g_V[ia] = ta;
                    *(float2*)&g_V[ib] = tb;
                }
            } else {
                *(float2*)&out[(size_t)ma * NDIM + nb] = va;
                *(float2*)&out[(size_t)mb * NDIM + nb] = vb;
            }
        }
    }
}

// ============================================================
// Fused attention v5: 64-key tiles with pre-split K (hi/lo planes)
// and pre-rounded V -> inner loops are LDS+MMA only.
// 512 thr, 1 CTA/SM, cp.async double-buffered.
// ============================================================
__global__ __launch_bounds__(512, 1) void attn_kernel() {
    extern __shared__ float sm[];
    float* q_hi = sm;                   // 32*68  = 2176
    float* q_lo = sm + 2176;            // 2176
    float* sc   = sm + 4352;            // 32*1028 = 32896
    float* kb0  = sm + 37248;           // 2*64*72 = 9216 (hi @0, lo @4608)
    float* kb1  = sm + 46464;           // 9216
    float* invs = sm + 55680;           // 32
    // total 55712 floats = 222848 B

    const int t    = threadIdx.x;
    const int warp = t >> 5, lane = t & 31;
    const int gid  = lane >> 2, tig = lane & 3;
    const int bh = blockIdx.y;
    const int q0 = blockIdx.x * QT;
    const float* Qg  = g_Q  + (size_t)bh*Sq*Dd;
    const float* Khg = g_Kh + (size_t)bh*Sq*Dd;
    const float* Klg = g_Kl + (size_t)bh*Sq*Dd;
    const float* Vg  = g_V  + (size_t)bh*Sq*Dd;

    auto cp_ktile = [&](float* buf, int kt0) {   // 64 rows, hi+lo planes
        #pragma unroll
        for (int i = 0; i < 2; i++) {
            int f = t + 512*i;
            int row = f >> 4, c4 = (f & 15) << 2;
            cp16(&buf[row*KVP + c4], &Khg[(size_t)(kt0*KTK + row)*Dd + c4]);
        }
        #pragma unroll
        for (int i = 0; i < 2; i++) {
            int f = t + 512*i;
            int row = f >> 4, c4 = (f & 15) << 2;
            cp16(&buf[4608 + row*KVP + c4], &Klg[(size_t)(kt0*KTK + row)*Dd + c4]);
        }
        cp_commit();
    };
    auto cp_vtile = [&](float* buf, int kt0) {   // 64 rows, single plane
        #pragma unroll
        for (int i = 0; i < 2; i++) {
            int f = t + 512*i;
            int row = f >> 4, c4 = (f & 15) << 2;
            cp16(&buf[row*KVP + c4], &Vg[(size_t)(kt0*KTK + row)*Dd + c4]);
        }
        cp_commit();
    };

    cp_ktile(kb0, 0);
    {
        const int prow = t >> 4, pc4 = (t & 15) << 2;
        float4 v = *(const float4*)&Qg[(size_t)(q0 + prow)*Dd + pc4];
        v.x *= 0.125f; v.y *= 0.125f; v.z *= 0.125f; v.w *= 0.125f;
        uint32_t h, l;
        split_tf32(v.x, h, l); q_hi[prow*QSP + pc4+0] = __uint_as_float(h); q_lo[prow*QSP + pc4+0] = __uint_as_float(l);
        split_tf32(v.y, h, l); q_hi[prow*QSP + pc4+1] = __uint_as_float(h); q_lo[prow*QSP + pc4+1] = __uint_as_float(l);
        split_tf32(v.z, h, l); q_hi[prow*QSP + pc4+2] = __uint_as_float(h); q_lo[prow*QSP + pc4+2] = __uint_as_float(l);
        split_tf32(v.w, h, l); q_hi[prow*QSP + pc4+3] = __uint_as_float(h); q_lo[prow*QSP + pc4+3] = __uint_as_float(l);
    }
    __syncthreads();

    // warp's q-half and 8-key group; q fragments loop-invariant in regs
    const int qh_  = warp >> 3;
    const int key0 = (warp & 7) * 8;
    const int r0 = qh_*16 + gid, r1 = r0 + 8;
    uint32_t qfh[8][4], qfl[8][4];
    #pragma unroll
    for (int ks = 0; ks < 8; ks++) {
        qfh[ks][0] = __float_as_uint(q_hi[r0*QSP + ks*8 + tig    ]);
        qfh[ks][1] = __float_as_uint(q_hi[r1*QSP + ks*8 + tig    ]);
        qfh[ks][2] = __float_as_uint(q_hi[r0*QSP + ks*8 + tig + 4]);
        qfh[ks][3] = __float_as_uint(q_hi[r1*QSP + ks*8 + tig + 4]);
        qfl[ks][0] = __float_as_uint(q_lo[r0*QSP + ks*8 + tig    ]);
        qfl[ks][1] = __float_as_uint(q_lo[r1*QSP + ks*8 + tig    ]);
        qfl[ks][2] = __float_as_uint(q_lo[r0*QSP + ks*8 + tig + 4]);
        qfl[ks][3] = __float_as_uint(q_lo[r1*QSP + ks*8 + tig + 4]);
    }

    // ================= scores (3xTF32, pure LDS+MMA) =================
    for (int it = 0; it < 16; it++) {
        if (it + 1 < 16) { cp_ktile((it & 1) ? kb0 : kb1, it + 1); cp_wait<1>(); }
        else             { cp_wait<0>(); }
        __syncthreads();
        const float* KH = (it & 1) ? kb1 : kb0;
        const float* KL = KH + 4608;

        float4 ca = make_float4(0.f,0.f,0.f,0.f), cb2 = ca;
        #pragma unroll
        for (int ks = 0; ks < 8; ks++) {
            uint32_t Bh[2], Bl[2];
            Bh[0] = __float_as_uint(KH[(key0 + gid)*KVP + ks*8 + tig    ]);
            Bh[1] = __float_as_uint(KH[(key0 + gid)*KVP + ks*8 + tig + 4]);
            Bl[0] = __float_as_uint(KL[(key0 + gid)*KVP + ks*8 + tig    ]);
            Bl[1] = __float_as_uint(KL[(key0 + gid)*KVP + ks*8 + tig + 4]);
            float4& c = (ks & 1) ? cb2 : ca;
            mma_tf32(c, qfl[ks], Bh); mma_tf32(c, qfh[ks], Bl); mma_tf32(c, qfh[ks], Bh);
        }
        float4 c0 = make_float4(ca.x+cb2.x, ca.y+cb2.y, ca.z+cb2.z, ca.w+cb2.w);
        const int cb = it*KTK + key0 + 2*tig;
        *(float2*)&sc[r0*SCP + cb] = make_float2(c0.x, c0.y);
        *(float2*)&sc[r1*SCP + cb] = make_float2(c0.z, c0.w);
        __syncthreads();
    }

    cp_vtile(kb0, 0);   // V0 flies during top-k

    // ====== exact top-k via bit-plane radix select + softmax ======
    {
        const int lane5 = t & 31;
        #pragma unroll 1
        for (int r = warp*2; r < warp*2 + 2; r++) {
            float* row = sc + r*SCP;
            unsigned u[32], tp[32];
            float mx = -3.4e38f;
            #pragma unroll
            for (int i = 0; i < 32; i++) {
                float f = row[i*32 + lane5];
                mx = fmaxf(mx, f);
                unsigned b = __float_as_uint(f);
                u[i] = b ^ (unsigned)(((int)b >> 31) | (int)0x80000000);
                tp[i] = u[i];
            }
            #pragma unroll
            for (int o = 16; o; o >>= 1) mx = fmaxf(mx, __shfl_xor_sync(0xffffffffu, mx, o));

            bit_transpose32(tp);

            unsigned active = 0xffffffffu, pref = 0;
            int kr = TOPK, asz = 1024;
            #pragma unroll
            for (int idx = 0; idx < 32; idx++) {
                unsigned s = active & tp[idx];
                int ctot = (int)__reduce_add_sync(0xffffffffu, (unsigned)__popc(s));
                if (ctot >= kr) { active = s; asz = ctot; pref |= (1u << (31 - idx)); }
                else            { kr -= ctot; active &= ~s; asz -= ctot; }
                if (asz == kr) break;
            }
            unsigned mn = 0xffffffffu;
            #pragma unroll
            for (int i = 0; i < 32; i++)
                if (u[i] >= pref) mn = min(mn, u[i]);
            mn = __reduce_min_sync(0xffffffffu, mn);

            float ssum = 0.f;
            #pragma unroll
            for (int i = 0; i < 32; i++) {
                float p = 0.f;
                if (u[i] >= mn) {
                    unsigned b = (u[i] & 0x80000000u) ? (u[i] ^ 0x80000000u) : ~u[i];
                    p = __expf(__uint_as_float(b) - mx);
                }
                ssum += p;
                row[i*32 + lane5] = __uint_as_float(f2tf(p));
            }
            #pragma unroll
            for (int o = 16; o; o >>= 1) ssum += __shfl_xor_sync(0xffffffffu, ssum, o);
            if (lane5 == 0) invs[r] = 1.f / ssum;
        }
    }
    cp_wait<0>(); __syncthreads();   // V0 in smem; p + invs visible

    // ============ PV (1xTF32, pure LDS+MMA; chain map preserves R11 order) ============
    const int dc = (warp & 7) * 8;
    float4 oc[4];
    #pragma unroll
    for (int j = 0; j < 4; j++) oc[j] = make_float4(0.f,0.f,0.f,0.f);

    for (int it = 0; it < 16; it++) {
        if (it + 1 < 16) { cp_vtile((it & 1) ? kb0 : kb1, it + 1); cp_wait<1>(); }
        else             { cp_wait<0>(); }
        __syncthreads();
        const float* VT = (it & 1) ? kb1 : kb0;
        const int kb = it*KTK;
        #pragma unroll
        for (int ks = 0; ks < 8; ks++) {
            uint32_t Ap[4], Bv[2];
            Ap[0] = __float_as_uint(sc[r0*SCP + kb + ks*8 + tig    ]);
            Ap[1] = __float_as_uint(sc[r1*SCP + kb + ks*8 + tig    ]);
            Ap[2] = __float_as_uint(sc[r0*SCP + kb + ks*8 + tig + 4]);
            Ap[3] = __float_as_uint(sc[r1*SCP + kb + ks*8 + tig + 4]);
            Bv[0] = __float_as_uint(VT[(ks*8 + tig    )*KVP + dc + gid]);
            Bv[1] = __float_as_uint(VT[(ks*8 + tig + 4)*KVP + dc + gid]);
            mma_tf32(oc[((it & 1) << 1) | (ks >> 2)], Ap, Bv);
        }
        __syncthreads();
    }

    // epilogue
    {
        float4 o;
        o.x = (oc[0].x + oc[1].x) + (oc[2].x + oc[3].x);
        o.y = (oc[0].y + oc[1].y) + (oc[2].y + oc[3].y);
        o.z = (oc[0].z + oc[1].z) + (oc[2].z + oc[3].z);
        o.w = (oc[0].w + oc[1].w) + (oc[2].w + oc[3].w);
        const int bb = bh / Hh, hh = bh % Hh;
        const float iv0 = invs[r0], iv1 = invs[r1];
        const int d0 = dc + 2*tig;
        *(float2*)&g_AO[(size_t)((bb*Sq + q0 + r0)*Hh + hh)*Dd + d0] = make_float2(o.x*iv0, o.y*iv0);
        *(float2*)&g_AO[(size_t)((bb*Sq + q0 + r1)*Hh + hh)*Dd + d0] = make_float2(o.z*iv1, o.w*iv1);
    }
}

// ============================================================
// launch
// ============================================================
extern "C" void kernel_launch(void* const* d_in, const int* in_sizes, int n_in,
                              void* d_out, int out_size) {
    const float* hidden = (const float*)d_in[0];
    const float* Wqkv   = (const float*)d_in[1];
    const float* bqkv   = (const float*)d_in[2];
    const float* Wproj  = (const float*)d_in[3];
    const float* bproj  = (const float*)d_in[4];
    float* out = (float*)d_out;

    const int attn_smem = 55712 * (int)sizeof(float);  // 222848 B
    cudaFuncSetAttribute(attn_kernel, cudaFuncAttributeMaxDynamicSharedMemorySize, attn_smem);

    gemm_tf32<N3, true ><<<dim3(N3/128, (Bz*Sq)/128), 256>>>(hidden, Wqkv, bqkv, nullptr);
    attn_kernel<<<dim3(Sq/QT, Bz*Hh), 512, attn_smem>>>();
    gemm_tf32<Ed, false><<<dim3(Ed/128, (Bz*Sq)/128), 256>>>(nullptr, Wproj, bproj, out);
}

// round 15
// speedup vs baseline: 1.0937x; 1.0937x over previous
#include <cuda_runtime.h>
#include <cstdint>

#define Bz 8
#define Sq 1024
#define Ed 768
#define Hh 12
#define Dd 64
#define N3 2304
#define TOPK 409
#define QT 32
#define KTT 128
#define KVP 72
#define QSP 68
#define SCP 1028

#define ASTR 20
#define BSTR 136

// ---- scratch (allocation-free rule: __device__ globals) ----
__device__ float g_Q [Bz*Hh*Sq*Dd];
__device__ float g_K [Bz*Hh*Sq*Dd];
__device__ float g_V [Bz*Hh*Sq*Dd];   // pre-rounded to tf32 (idempotent)
__device__ float g_AO[Bz*Sq*Ed];      // [b,s,h,d] = [8192, 768]

// ---- cp.async helpers ----
__device__ __forceinline__ void cp16(void* smem_dst, const void* gmem_src) {
    unsigned s = (unsigned)__cvta_generic_to_shared(smem_dst);
    asm volatile("cp.async.cg.shared.global [%0], [%1], 16;" :: "r"(s), "l"(gmem_src));
}
__device__ __forceinline__ void cp_commit() { asm volatile("cp.async.commit_group;"); }
template<int N>
__device__ __forceinline__ void cp_wait() { asm volatile("cp.async.wait_group %0;" :: "n"(N)); }

// ---- tf32 helpers ----
__device__ __forceinline__ uint32_t f2tf(float x) {
    uint32_t r; asm("cvt.rna.tf32.f32 %0, %1;" : "=r"(r) : "f"(x)); return r;
}
__device__ __forceinline__ void split_tf32(float x, uint32_t& hi, uint32_t& lo) {
    uint32_t h;
    asm("cvt.rna.tf32.f32 %0, %1;" : "=r"(h) : "f"(x));
    float l = x - __uint_as_float(h);
    uint32_t lw;
    asm("cvt.rna.tf32.f32 %0, %1;" : "=r"(lw) : "f"(l));
    hi = h; lo = lw;
}
__device__ __forceinline__ void mma_tf32(float4& d, const uint32_t a[4], const uint32_t b[2]) {
    asm volatile("mma.sync.aligned.m16n8k8.row.col.f32.tf32.tf32.f32 "
                 "{%0,%1,%2,%3}, {%4,%5,%6,%7}, {%8,%9}, {%0,%1,%2,%3};"
                 : "+f"(d.x), "+f"(d.y), "+f"(d.z), "+f"(d.w)
                 : "r"(a[0]), "r"(a[1]), "r"(a[2]), "r"(a[3]), "r"(b[0]), "r"(b[1]));
}

// ---- 32x32 bit-matrix transpose (Hacker's Delight 7-7) ----
template<int J>
__device__ __forceinline__ void tstage(unsigned a[32], unsigned m) {
    #pragma unroll
    for (int g = 0; g < 16; g++) {
        const int k = ((g & ~(J - 1)) << 1) | (g & (J - 1));
        unsigned t = (a[k] ^ (a[k + J] >> J)) & m;
        a[k]     ^= t;
        a[k + J] ^= (t << J);
    }
}
__device__ __forceinline__ void bit_transpose32(unsigned a[32]) {
    tstage<16>(a, 0x0000FFFFu);
    tstage<8> (a, 0x00FF00FFu);
    tstage<4> (a, 0x0F0F0F0Fu);
    tstage<2> (a, 0x33333333u);
    tstage<1> (a, 0x55555555u);
}

// ============================================================
// 3xTF32 GEMM, single-sync pipeline (wait->sync->issue->compute).
// Epilogue: Q/K plain fp32, V pre-rounded tf32.
// ============================================================
template<int NDIM, bool SCATTER>
__global__ __launch_bounds__(256, 2) void gemm_tf32(const float* __restrict__ A_in,
                                                    const float* __restrict__ W,
                                                    const float* __restrict__ bias,
                                                    float* __restrict__ out) {
    const float* A = SCATTER ? A_in : (const float*)g_AO;   // device-side symbol!

    __shared__ float As[2][128*ASTR];
    __shared__ float Bs[2][16*BSTR];

    const int t    = threadIdx.x;
    const int warp = t >> 5, lane = t & 31;
    const int gid  = lane >> 2, tig = lane & 3;
    const int m0   = blockIdx.y * 128, n0 = blockIdx.x * 128;
    const int wm   = (warp >> 2) * 64;
    const int wn   = (warp & 3) * 32;

    auto issue = [&](int buf, int kt) {
        #pragma unroll
        for (int i = 0; i < 2; i++) {
            int f = t + 256*i;
            int m = f >> 2, kc = (f & 3) << 2;
            cp16(&As[buf][m*ASTR + kc], &A[(size_t)(m0 + m)*Ed + kt*16 + kc]);
        }
        #pragma unroll
        for (int i = 0; i < 2; i++) {
            int f = t + 256*i;
            int kr = f >> 5, nc = (f & 31) << 2;
            cp16(&Bs[buf][kr*BSTR + nc], &W[(size_t)(kt*16 + kr)*NDIM + n0 + nc]);
        }
        cp_commit();
    };

    float4 acc[4][4];
    #pragma unroll
    for (int i = 0; i < 4; i++)
        #pragma unroll
        for (int j = 0; j < 4; j++) acc[i][j] = make_float4(0.f, 0.f, 0.f, 0.f);

    issue(0, 0);
    const int NT = Ed / 16;  // 48
    for (int kt = 0; kt < NT; kt++) {
        cp_wait<0>();        // tile kt landed
        __syncthreads();     // tile kt visible; reads of buf (kt+1)&1 (iter kt-1) done
        if (kt + 1 < NT) issue((kt + 1) & 1, kt + 1);
        const float* as = As[kt & 1];
        const float* bs = Bs[kt & 1];
        #pragma unroll
        for (int ko = 0; ko < 16; ko += 8) {
            uint32_t Bhi[4][2], Blo[4][2];
            #pragma unroll
            for (int j = 0; j < 4; j++) {
                const int nc = wn + 8*j + gid;
                split_tf32(bs[(ko + tig    )*BSTR + nc], Bhi[j][0], Blo[j][0]);
                split_tf32(bs[(ko + tig + 4)*BSTR + nc], Bhi[j][1], Blo[j][1]);
            }
            #pragma unroll
            for (int i = 0; i < 4; i++) {
                const int r0 = wm + 16*i + gid;
                uint32_t Ahi[4], Alo[4];
                split_tf32(as[ r0     *ASTR + ko + tig    ], Ahi[0], Alo[0]);
                split_tf32(as[(r0 + 8)*ASTR + ko + tig    ], Ahi[1], Alo[1]);
                split_tf32(as[ r0     *ASTR + ko + tig + 4], Ahi[2], Alo[2]);
                split_tf32(as[(r0 + 8)*ASTR + ko + tig + 4], Ahi[3], Alo[3]);
                #pragma unroll
                for (int j = 0; j < 4; j++) {
                    mma_tf32(acc[i][j], Alo, Bhi[j]);
                    mma_tf32(acc[i][j], Ahi, Blo[j]);
                    mma_tf32(acc[i][j], Ahi, Bhi[j]);
                }
            }
        }
    }

    #pragma unroll
    for (int i = 0; i < 4; i++) {
        const int ma = m0 + wm + 16*i + gid;
        const int mb = ma + 8;
        #pragma unroll
        for (int j = 0; j < 4; j++) {
            const int nb = n0 + wn + 8*j + 2*tig;
            const float2 bv = *(const float2*)&bias[nb];
            float2 va = make_float2(acc[i][j].x + bv.x, acc[i][j].y + bv.y);
            float2 vb = make_float2(acc[i][j].z + bv.x, acc[i][j].w + bv.y);
            if (SCATTER) {
                const int which = nb / Ed;
                const int hh    = (nb % Ed) >> 6;
                const int d0    = nb & 63;
                const int ba = ma >> 10, sa = ma & 1023;
                const int bbq = mb >> 10, sb = mb & 1023;
                const size_t ia = (size_t)((ba*Hh + hh)*Sq + sa)*Dd + d0;
                const size_t ib = (size_t)((bbq*Hh + hh)*Sq + sb)*Dd + d0;
                if (which == 2) {   // V: pre-round to tf32 (idempotent)
                    float2 ta, tb;
                    ta.x = __uint_as_float(f2tf(va.x)); ta.y = __uint_as_float(f2tf(va.y));
                    tb.x = __uint_as_float(f2tf(vb.x)); tb.y = __uint_as_float(f2tf(vb.y));
                    *(float2*)&g_V[ia] = ta;
                    *(float2*)&g_V[ib] = tb;
                } else {
                    float* dst = (which == 0) ? g_Q : g_K;
                    *(float2*)&dst[ia] = va;
                    *(float2*)&dst[ib] = vb;
                }
            } else {
                *(float2*)&out[(size_t)ma * NDIM + nb] = va;
                *(float2*)&out[(size_t)mb * NDIM + nb] = vb;
            }
        }
    }
}

// ============================================================
// Fused attention (R11 tiles, single-sync pipelines, V pre-tf32)
// 512 thr, 1 CTA/SM, 128-row K/V tiles double-buffered.
// ============================================================
__global__ __launch_bounds__(512, 1) void attn_kernel() {
    extern __shared__ float sm[];
    float* q_hi = sm;                   // 32*68  = 2176
    float* q_lo = sm + 2176;            // 2176
    float* sc   = sm + 4352;            // 32*1028 = 32896
    float* kv0  = sm + 37248;           // 128*72 = 9216
    float* kv1  = sm + 46464;           // 9216
    float* invs = sm + 55680;           // 32
    // total 55712 floats = 222848 B

    const int t    = threadIdx.x;
    const int warp = t >> 5, lane = t & 31;
    const int gid  = lane >> 2, tig = lane & 3;
    const int bh = blockIdx.y;
    const int q0 = blockIdx.x * QT;
    const float* Qg = g_Q + (size_t)bh*Sq*Dd;
    const float* Kg = g_K + (size_t)bh*Sq*Dd;
    const float* Vg = g_V + (size_t)bh*Sq*Dd;

    auto cp_tile = [&](float* buf, const float* src, int kt0) {
        #pragma unroll
        for (int i = 0; i < 4; i++) {
            int f = t + 512*i;
            int row = f >> 4, c4 = (f & 15) << 2;
            cp16(&buf[row*KVP + c4], &src[(size_t)(kt0*KTT + row)*Dd + c4]);
        }
        cp_commit();
    };

    cp_tile(kv0, Kg, 0);
    {
        const int prow = t >> 4, pc4 = (t & 15) << 2;
        float4 v = *(const float4*)&Qg[(size_t)(q0 + prow)*Dd + pc4];
        v.x *= 0.125f; v.y *= 0.125f; v.z *= 0.125f; v.w *= 0.125f;
        uint32_t h, l;
        split_tf32(v.x, h, l); q_hi[prow*QSP + pc4+0] = __uint_as_float(h); q_lo[prow*QSP + pc4+0] = __uint_as_float(l);
        split_tf32(v.y, h, l); q_hi[prow*QSP + pc4+1] = __uint_as_float(h); q_lo[prow*QSP + pc4+1] = __uint_as_float(l);
        split_tf32(v.z, h, l); q_hi[prow*QSP + pc4+2] = __uint_as_float(h); q_lo[prow*QSP + pc4+2] = __uint_as_float(l);
        split_tf32(v.w, h, l); q_hi[prow*QSP + pc4+3] = __uint_as_float(h); q_lo[prow*QSP + pc4+3] = __uint_as_float(l);
    }
    __syncthreads();

    const int qh_  = warp >> 3;
    const int key0 = (warp & 7) * 16;
    const int r0 = qh_*16 + gid, r1 = r0 + 8;
    uint32_t qfh[8][4], qfl[8][4];
    #pragma unroll
    for (int ks = 0; ks < 8; ks++) {
        qfh[ks][0] = __float_as_uint(q_hi[r0*QSP + ks*8 + tig    ]);
        qfh[ks][1] = __float_as_uint(q_hi[r1*QSP + ks*8 + tig    ]);
        qfh[ks][2] = __float_as_uint(q_hi[r0*QSP + ks*8 + tig + 4]);
        qfh[ks][3] = __float_as_uint(q_hi[r1*QSP + ks*8 + tig + 4]);
        qfl[ks][0] = __float_as_uint(q_lo[r0*QSP + ks*8 + tig    ]);
        qfl[ks][1] = __float_as_uint(q_lo[r1*QSP + ks*8 + tig    ]);
        qfl[ks][2] = __float_as_uint(q_lo[r0*QSP + ks*8 + tig + 4]);
        qfl[ks][3] = __float_as_uint(q_lo[r1*QSP + ks*8 + tig + 4]);
    }

    // ======== scores (3xTF32), ONE sync per tile iteration ========
    for (int it = 0; it < 8; it++) {
        cp_wait<0>();
        __syncthreads();   // tile it visible; reads of the OTHER buffer (iter it-1) done
        if (it + 1 < 8) cp_tile((it & 1) ? kv0 : kv1, Kg, it + 1);   // it even -> kv1 (FIXED)
        const float* kb_ = (it & 1) ? kv1 : kv0;

        float4 c0a = make_float4(0.f,0.f,0.f,0.f), c0b = c0a, c1a = c0a, c1b = c0a;
        #pragma unroll
        for (int ks = 0; ks < 8; ks++) {
            uint32_t Bh[2], Bl[2];
            split_tf32(kb_[(key0     + gid)*KVP + ks*8 + tig    ], Bh[0], Bl[0]);
            split_tf32(kb_[(key0     + gid)*KVP + ks*8 + tig + 4], Bh[1], Bl[1]);
            float4& c0 = (ks & 1) ? c0b : c0a;
            mma_tf32(c0, qfl[ks], Bh); mma_tf32(c0, qfh[ks], Bl); mma_tf32(c0, qfh[ks], Bh);
            split_tf32(kb_[(key0 + 8 + gid)*KVP + ks*8 + tig    ], Bh[0], Bl[0]);
            split_tf32(kb_[(key0 + 8 + gid)*KVP + ks*8 + tig + 4], Bh[1], Bl[1]);
            float4& c1 = (ks & 1) ? c1b : c1a;
            mma_tf32(c1, qfl[ks], Bh); mma_tf32(c1, qfh[ks], Bl); mma_tf32(c1, qfh[ks], Bh);
        }
        float4 c0 = make_float4(c0a.x+c0b.x, c0a.y+c0b.y, c0a.z+c0b.z, c0a.w+c0b.w);
        float4 c1 = make_float4(c1a.x+c1b.x, c1a.y+c1b.y, c1a.z+c1b.z, c1a.w+c1b.w);
        const int cb = it*KTT + key0 + 2*tig;
        *(float2*)&sc[r0*SCP + cb    ] = make_float2(c0.x, c0.y);
        *(float2*)&sc[r1*SCP + cb    ] = make_float2(c0.z, c0.w);
        *(float2*)&sc[r0*SCP + cb + 8] = make_float2(c1.x, c1.y);
        *(float2*)&sc[r1*SCP + cb + 8] = make_float2(c1.z, c1.w);
    }

    // V0 into kv0 (kv0 last read at it=6; all warps passed it=7's sync)
    cp_tile(kv0, Vg, 0);
    __syncthreads();   // sc writes visible before cross-warp top-k reads

    // ====== exact top-k via bit-plane radix select + softmax ======
    {
        const int lane5 = t & 31;
        #pragma unroll 1
        for (int r = warp*2; r < warp*2 + 2; r++) {
            float* row = sc + r*SCP;
            unsigned u[32], tp[32];
            float mx = -3.4e38f;
            #pragma unroll
            for (int i = 0; i < 32; i++) {
                float f = row[i*32 + lane5];
                mx = fmaxf(mx, f);
                unsigned b = __float_as_uint(f);
                u[i] = b ^ (unsigned)(((int)b >> 31) | (int)0x80000000);
                tp[i] = u[i];
            }
            #pragma unroll
            for (int o = 16; o; o >>= 1) mx = fmaxf(mx, __shfl_xor_sync(0xffffffffu, mx, o));

            bit_transpose32(tp);

            unsigned active = 0xffffffffu, pref = 0;
            int kr = TOPK, asz = 1024;
            #pragma unroll
            for (int idx = 0; idx < 32; idx++) {
                unsigned s = active & tp[idx];
                int ctot = (int)__reduce_add_sync(0xffffffffu, (unsigned)__popc(s));
                if (ctot >= kr) { active = s; asz = ctot; pref |= (1u << (31 - idx)); }
                else            { kr -= ctot; active &= ~s; asz -= ctot; }
                if (asz == kr) break;
            }
            unsigned mn = 0xffffffffu;
            #pragma unroll
            for (int i = 0; i < 32; i++)
                if (u[i] >= pref) mn = min(mn, u[i]);
            mn = __reduce_min_sync(0xffffffffu, mn);

            float ssum = 0.f;
            #pragma unroll
            for (int i = 0; i < 32; i++) {
                float p = 0.f;
                if (u[i] >= mn) {
                    unsigned b = (u[i] & 0x80000000u) ? (u[i] ^ 0x80000000u) : ~u[i];
                    p = __expf(__uint_as_float(b) - mx);
                }
                ssum += p;
                row[i*32 + lane5] = __uint_as_float(f2tf(p));
            }
            #pragma unroll
            for (int o = 16; o; o >>= 1) ssum += __shfl_xor_sync(0xffffffffu, ssum, o);
            if (lane5 == 0) invs[r] = 1.f / ssum;
        }
    }

    // ======== PV (1xTF32, V already tf32), ONE sync per iteration ========
    const int dc = (warp & 7) * 8;
    float4 oc[4];
    #pragma unroll
    for (int j = 0; j < 4; j++) oc[j] = make_float4(0.f,0.f,0.f,0.f);

    for (int it = 0; it < 8; it++) {
        cp_wait<0>();
        __syncthreads();   // V tile it visible; p/invs visible at it=0; WAR on other buf done
        if (it + 1 < 8) cp_tile((it & 1) ? kv0 : kv1, Vg, it + 1);   // it even -> kv1 (FIXED)
        const float* kb_ = (it & 1) ? kv1 : kv0;
        const int kb = it*KTT;
        #pragma unroll
        for (int ks = 0; ks < 16; ks++) {
            uint32_t Ap[4], Bv[2];
            Ap[0] = __float_as_uint(sc[r0*SCP + kb + ks*8 + tig    ]);
            Ap[1] = __float_as_uint(sc[r1*SCP + kb + ks*8 + tig    ]);
            Ap[2] = __float_as_uint(sc[r0*SCP + kb + ks*8 + tig + 4]);
            Ap[3] = __float_as_uint(sc[r1*SCP + kb + ks*8 + tig + 4]);
            Bv[0] = __float_as_uint(kb_[(ks*8 + tig    )*KVP + dc + gid]);
            Bv[1] = __float_as_uint(kb_[(ks*8 + tig + 4)*KVP + dc + gid]);
            mma_tf32(oc[ks >> 2], Ap, Bv);
        }
    }

    // epilogue
    {
        float4 o;
        o.x = (oc[0].x + oc[1].x) + (oc[2].x + oc[3].x);
        o.y = (oc[0].y + oc[1].y) + (oc[2].y + oc[3].y);
        o.z = (oc[0].z + oc[1].z) + (oc[2].z + oc[3].z);
        o.w = (oc[0].w + oc[1].w) + (oc[2].w + oc[3].w);
        const int bb = bh / Hh, hh = bh % Hh;
        const float iv0 = invs[r0], iv1 = invs[r1];
        const int d0 = dc + 2*tig;
        *(float2*)&g_AO[(size_t)((bb*Sq + q0 + r0)*Hh + hh)*Dd + d0] = make_float2(o.x*iv0, o.y*iv0);
        *(float2*)&g_AO[(size_t)((bb*Sq + q0 + r1)*Hh + hh)*Dd + d0] = make_float2(o.z*iv1, o.w*iv1);
    }
}

// ============================================================
// launch
// ============================================================
extern "C" void kernel_launch(void* const* d_in, const int* in_sizes, int n_in,
                              void* d_out, int out_size) {
    const float* hidden = (const float*)d_in[0];
    const float* Wqkv   = (const float*)d_in[1];
    const float* bqkv   = (const float*)d_in[2];
    const float* Wproj  = (const float*)d_in[3];
    const float* bproj  = (const float*)d_in[4];
    float* out = (float*)d_out;

    const int attn_smem = 55712 * (int)sizeof(float);  // 222848 B
    cudaFuncSetAttribute(attn_kernel, cudaFuncAttributeMaxDynamicSharedMemorySize, attn_smem);

    gemm_tf32<N3, true ><<<dim3(N3/128, (Bz*Sq)/128), 256>>>(hidden, Wqkv, bqkv, nullptr);
    attn_kernel<<<dim3(Sq/QT, Bz*Hh), 512, attn_smem>>>();
    gemm_tf32<Ed, false><<<dim3(Ed/128, (Bz*Sq)/128), 256>>>(nullptr, Wproj, bproj, out);
}

// round 16
// speedup vs baseline: 1.1937x; 1.0915x over previous
#include <cuda_runtime.h>
#include <cstdint>

#define Bz 8
#define Sq 1024
#define Ed 768
#define Hh 12
#define Dd 64
#define N3 2304
#define TOPK 409
#define QT 32
#define KTT 128
#define KVP 72
#define QBP 34     // packed q plane row stride (words of bf16x2)
#define SCP 1028

#define ASTR 20
#define BSTR 136

// ---- scratch (allocation-free rule: __device__ globals) ----
__device__ float g_Q [Bz*Hh*Sq*Dd];
__device__ float g_K [Bz*Hh*Sq*Dd];
__device__ float g_V [Bz*Hh*Sq*Dd];   // pre-rounded to tf32 (idempotent)
__device__ float g_AO[Bz*Sq*Ed];      // [b,s,h,d] = [8192, 768]

// ---- cp.async helpers ----
__device__ __forceinline__ void cp16(void* smem_dst, const void* gmem_src) {
    unsigned s = (unsigned)__cvta_generic_to_shared(smem_dst);
    asm volatile("cp.async.cg.shared.global [%0], [%1], 16;" :: "r"(s), "l"(gmem_src));
}
__device__ __forceinline__ void cp_commit() { asm volatile("cp.async.commit_group;"); }
template<int N>
__device__ __forceinline__ void cp_wait() { asm volatile("cp.async.wait_group %0;" :: "n"(N)); }

// ---- tf32 helpers ----
__device__ __forceinline__ uint32_t f2tf(float x) {
    uint32_t r; asm("cvt.rna.tf32.f32 %0, %1;" : "=r"(r) : "f"(x)); return r;
}
__device__ __forceinline__ void split_tf32(float x, uint32_t& hi, uint32_t& lo) {
    uint32_t h;
    asm("cvt.rna.tf32.f32 %0, %1;" : "=r"(h) : "f"(x));
    float l = x - __uint_as_float(h);
    uint32_t lw;
    asm("cvt.rna.tf32.f32 %0, %1;" : "=r"(lw) : "f"(l));
    hi = h; lo = lw;
}
__device__ __forceinline__ void mma_tf32(float4& d, const uint32_t a[4], const uint32_t b[2]) {
    asm volatile("mma.sync.aligned.m16n8k8.row.col.f32.tf32.tf32.f32 "
                 "{%0,%1,%2,%3}, {%4,%5,%6,%7}, {%8,%9}, {%0,%1,%2,%3};"
                 : "+f"(d.x), "+f"(d.y), "+f"(d.z), "+f"(d.w)
                 : "r"(a[0]), "r"(a[1]), "r"(a[2]), "r"(a[3]), "r"(b[0]), "r"(b[1]));
}

// ---- bf16x2 helpers ----
// pack: lo half = first arg, hi half = second arg
__device__ __forceinline__ uint32_t pack_bf16(float lo, float hi) {
    uint32_t r; asm("cvt.rn.bf16x2.f32 %0, %1, %2;" : "=r"(r) : "f"(hi), "f"(lo)); return r;
}
__device__ __forceinline__ float bf_lo(uint32_t p) { return __uint_as_float(p << 16); }
__device__ __forceinline__ float bf_hi(uint32_t p) { return __uint_as_float(p & 0xFFFF0000u); }
__device__ __forceinline__ void mma_bf16(float4& d, const uint32_t a[4], const uint32_t b[2]) {
    asm volatile("mma.sync.aligned.m16n8k16.row.col.f32.bf16.bf16.f32 "
                 "{%0,%1,%2,%3}, {%4,%5,%6,%7}, {%8,%9}, {%0,%1,%2,%3};"
                 : "+f"(d.x), "+f"(d.y), "+f"(d.z), "+f"(d.w)
                 : "r"(a[0]), "r"(a[1]), "r"(a[2]), "r"(a[3]), "r"(b[0]), "r"(b[1]));
}

// ---- 32x32 bit-matrix transpose (Hacker's Delight 7-7) ----
template<int J>
__device__ __forceinline__ void tstage(unsigned a[32], unsigned m) {
    #pragma unroll
    for (int g = 0; g < 16; g++) {
        const int k = ((g & ~(J - 1)) << 1) | (g & (J - 1));
        unsigned t = (a[k] ^ (a[k + J] >> J)) & m;
        a[k]     ^= t;
        a[k + J] ^= (t << J);
    }
}
__device__ __forceinline__ void bit_transpose32(unsigned a[32]) {
    tstage<16>(a, 0x0000FFFFu);
    tstage<8> (a, 0x00FF00FFu);
    tstage<4> (a, 0x0F0F0F0Fu);
    tstage<2> (a, 0x33333333u);
    tstage<1> (a, 0x55555555u);
}

// ============================================================
// 3xTF32 GEMM (R15, passing). Epilogue: Q/K fp32, V pre-tf32.
// ============================================================
template<int NDIM, bool SCATTER>
__global__ __launch_bounds__(256, 2) void gemm_tf32(const float* __restrict__ A_in,
                                                    const float* __restrict__ W,
                                                    const float* __restrict__ bias,
                                                    float* __restrict__ out) {
    const float* A = SCATTER ? A_in : (const float*)g_AO;   // device-side symbol!

    __shared__ float As[2][128*ASTR];
    __shared__ float Bs[2][16*BSTR];

    const int t    = threadIdx.x;
    const int warp = t >> 5, lane = t & 31;
    const int gid  = lane >> 2, tig = lane & 3;
    const int m0   = blockIdx.y * 128, n0 = blockIdx.x * 128;
    const int wm   = (warp >> 2) * 64;
    const int wn   = (warp & 3) * 32;

    auto issue = [&](int buf, int kt) {
        #pragma unroll
        for (int i = 0; i < 2; i++) {
            int f = t + 256*i;
            int m = f >> 2, kc = (f & 3) << 2;
            cp16(&As[buf][m*ASTR + kc], &A[(size_t)(m0 + m)*Ed + kt*16 + kc]);
        }
        #pragma unroll
        for (int i = 0; i < 2; i++) {
            int f = t + 256*i;
            int kr = f >> 5, nc = (f & 31) << 2;
            cp16(&Bs[buf][kr*BSTR + nc], &W[(size_t)(kt*16 + kr)*NDIM + n0 + nc]);
        }
        cp_commit();
    };

    float4 acc[4][4];
    #pragma unroll
    for (int i = 0; i < 4; i++)
        #pragma unroll
        for (int j = 0; j < 4; j++) acc[i][j] = make_float4(0.f, 0.f, 0.f, 0.f);

    issue(0, 0);
    const int NT = Ed / 16;  // 48
    for (int kt = 0; kt < NT; kt++) {
        cp_wait<0>();
        __syncthreads();
        if (kt + 1 < NT) issue((kt + 1) & 1, kt + 1);
        const float* as = As[kt & 1];
        const float* bs = Bs[kt & 1];
        #pragma unroll
        for (int ko = 0; ko < 16; ko += 8) {
            uint32_t Bhi[4][2], Blo[4][2];
            #pragma unroll
            for (int j = 0; j < 4; j++) {
                const int nc = wn + 8*j + gid;
                split_tf32(bs[(ko + tig    )*BSTR + nc], Bhi[j][0], Blo[j][0]);
                split_tf32(bs[(ko + tig + 4)*BSTR + nc], Bhi[j][1], Blo[j][1]);
            }
            #pragma unroll
            for (int i = 0; i < 4; i++) {
                const int r0 = wm + 16*i + gid;
                uint32_t Ahi[4], Alo[4];
                split_tf32(as[ r0     *ASTR + ko + tig    ], Ahi[0], Alo[0]);
                split_tf32(as[(r0 + 8)*ASTR + ko + tig    ], Ahi[1], Alo[1]);
                split_tf32(as[ r0     *ASTR + ko + tig + 4], Ahi[2], Alo[2]);
                split_tf32(as[(r0 + 8)*ASTR + ko + tig + 4], Ahi[3], Alo[3]);
                #pragma unroll
                for (int j = 0; j < 4; j++) {
                    mma_tf32(acc[i][j], Alo, Bhi[j]);
                    mma_tf32(acc[i][j], Ahi, Blo[j]);
                    mma_tf32(acc[i][j], Ahi, Bhi[j]);
                }
            }
        }
    }

    #pragma unroll
    for (int i = 0; i < 4; i++) {
        const int ma = m0 + wm + 16*i + gid;
        const int mb = ma + 8;
        #pragma unroll
        for (int j = 0; j < 4; j++) {
            const int nb = n0 + wn + 8*j + 2*tig;
            const float2 bv = *(const float2*)&bias[nb];
            float2 va = make_float2(acc[i][j].x + bv.x, acc[i][j].y + bv.y);
            float2 vb = make_float2(acc[i][j].z + bv.x, acc[i][j].w + bv.y);
            if (SCATTER) {
                const int which = nb / Ed;
                const int hh    = (nb % Ed) >> 6;
                const int d0    = nb & 63;
                const int ba = ma >> 10, sa = ma & 1023;
                const int bbq = mb >> 10, sb = mb & 1023;
                const size_t ia = (size_t)((ba*Hh + hh)*Sq + sa)*Dd + d0;
                const size_t ib = (size_t)((bbq*Hh + hh)*Sq + sb)*Dd + d0;
                if (which == 2) {
                    float2 ta, tb;
                    ta.x = __uint_as_float(f2tf(va.x)); ta.y = __uint_as_float(f2tf(va.y));
                    tb.x = __uint_as_float(f2tf(vb.x)); tb.y = __uint_as_float(f2tf(vb.y));
                    *(float2*)&g_V[ia] = ta;
                    *(float2*)&g_V[ib] = tb;
                } else {
                    float* dst = (which == 0) ? g_Q : g_K;
                    *(float2*)&dst[ia] = va;
                    *(float2*)&dst[ib] = vb;
                }
            } else {
                *(float2*)&out[(size_t)ma * NDIM + nb] = va;
                *(float2*)&out[(size_t)mb * NDIM + nb] = vb;
            }
        }
    }
}

// ============================================================
// Fused attention: bf16x2 scores (halved MMA work), exact radix
// top-k, 1xTF32 PV. 512 thr, 1 CTA/SM, single-sync pipelines.
// ============================================================
__global__ __launch_bounds__(512, 1) void attn_kernel() {
    extern __shared__ float sm[];
    uint32_t* q_b0 = (uint32_t*)sm;          // 32*34 = 1088 (bf16x2 hi plane)
    uint32_t* q_b1 = (uint32_t*)(sm + 1088); // 1088 (bf16x2 residual plane)
    float* sc   = sm + 2176;                 // 32*1028 = 32896
    float* kv0  = sm + 35072;                // 128*72 = 9216
    float* kv1  = sm + 44288;                // 9216
    float* invs = sm + 53504;                // 32
    // total 53536 floats = 214144 B

    const int t    = threadIdx.x;
    const int warp = t >> 5, lane = t & 31;
    const int gid  = lane >> 2, tig = lane & 3;
    const int bh = blockIdx.y;
    const int q0 = blockIdx.x * QT;
    const float* Qg = g_Q + (size_t)bh*Sq*Dd;
    const float* Kg = g_K + (size_t)bh*Sq*Dd;
    const float* Vg = g_V + (size_t)bh*Sq*Dd;

    auto cp_tile = [&](float* buf, const float* src, int kt0) {
        #pragma unroll
        for (int i = 0; i < 4; i++) {
            int f = t + 512*i;
            int row = f >> 4, c4 = (f & 15) << 2;
            cp16(&buf[row*KVP + c4], &src[(size_t)(kt0*KTT + row)*Dd + c4]);
        }
        cp_commit();
    };

    cp_tile(kv0, Kg, 0);
    // stage q: scale 0.125, split into bf16 hi + bf16 residual, packed pairs
    {
        const int prow = t >> 4, pc4 = (t & 15) << 2;   // 4 dims -> 2 packed words
        float4 v = *(const float4*)&Qg[(size_t)(q0 + prow)*Dd + pc4];
        v.x *= 0.125f; v.y *= 0.125f; v.z *= 0.125f; v.w *= 0.125f;
        uint32_t p0a = pack_bf16(v.x, v.y);
        uint32_t p0b = pack_bf16(v.z, v.w);
        uint32_t p1a = pack_bf16(v.x - bf_lo(p0a), v.y - bf_hi(p0a));
        uint32_t p1b = pack_bf16(v.z - bf_lo(p0b), v.w - bf_hi(p0b));
        const int w = pc4 >> 1;
        q_b0[prow*QBP + w]     = p0a;  q_b0[prow*QBP + w + 1] = p0b;
        q_b1[prow*QBP + w]     = p1a;  q_b1[prow*QBP + w + 1] = p1b;
    }
    __syncthreads();

    const int qh_  = warp >> 3;
    const int key0 = (warp & 7) * 16;
    const int r0 = qh_*16 + gid, r1 = r0 + 8;

    // q fragments for m16n8k16: 4 k16-steps, loop-invariant in registers
    uint32_t qa0[4][4], qa1[4][4];
    #pragma unroll
    for (int s = 0; s < 4; s++) {
        qa0[s][0] = q_b0[r0*QBP + s*8 + tig    ];
        qa0[s][1] = q_b0[r1*QBP + s*8 + tig    ];
        qa0[s][2] = q_b0[r0*QBP + s*8 + tig + 4];
        qa0[s][3] = q_b0[r1*QBP + s*8 + tig + 4];
        qa1[s][0] = q_b1[r0*QBP + s*8 + tig    ];
        qa1[s][1] = q_b1[r1*QBP + s*8 + tig    ];
        qa1[s][2] = q_b1[r0*QBP + s*8 + tig + 4];
        qa1[s][3] = q_b1[r1*QBP + s*8 + tig + 4];
    }

    // ======== scores (bf16x2: a1*b0 + a0*b1 + a0*b0 per k16) ========
    for (int it = 0; it < 8; it++) {
        cp_wait<0>();
        __syncthreads();
        if (it + 1 < 8) cp_tile((it & 1) ? kv0 : kv1, Kg, it + 1);
        const float* kb_ = (it & 1) ? kv1 : kv0;

        float4 c0a = make_float4(0.f,0.f,0.f,0.f), c0b = c0a, c1a = c0a, c1b = c0a;
        #pragma unroll
        for (int s = 0; s < 4; s++) {
            // n-tile 0: keys key0..key0+7
            {
                const int key = key0 + gid;
                float2 f01 = *(const float2*)&kb_[key*KVP + s*16 + 2*tig];
                float2 f89 = *(const float2*)&kb_[key*KVP + s*16 + 2*tig + 8];
                uint32_t b0[2], b1[2];
                b0[0] = pack_bf16(f01.x, f01.y);
                b0[1] = pack_bf16(f89.x, f89.y);
                b1[0] = pack_bf16(f01.x - bf_lo(b0[0]), f01.y - bf_hi(b0[0]));
                b1[1] = pack_bf16(f89.x - bf_lo(b0[1]), f89.y - bf_hi(b0[1]));
                float4& c = (s & 1) ? c0b : c0a;
                mma_bf16(c, qa1[s], b0); mma_bf16(c, qa0[s], b1); mma_bf16(c, qa0[s], b0);
            }
            // n-tile 1: keys key0+8..key0+15
            {
                const int key = key0 + 8 + gid;
                float2 f01 = *(const float2*)&kb_[key*KVP + s*16 + 2*tig];
                float2 f89 = *(const float2*)&kb_[key*KVP + s*16 + 2*tig + 8];
                uint32_t b0[2], b1[2];
                b0[0] = pack_bf16(f01.x, f01.y);
                b0[1] = pack_bf16(f89.x, f89.y);
                b1[0] = pack_bf16(f01.x - bf_lo(b0[0]), f01.y - bf_hi(b0[0]));
                b1[1] = pack_bf16(f89.x - bf_lo(b0[1]), f89.y - bf_hi(b0[1]));
                float4& c = (s & 1) ? c1b : c1a;
                mma_bf16(c, qa1[s], b0); mma_bf16(c, qa0[s], b1); mma_bf16(c, qa0[s], b0);
            }
        }
        float4 c0 = make_float4(c0a.x+c0b.x, c0a.y+c0b.y, c0a.z+c0b.z, c0a.w+c0b.w);
        float4 c1 = make_float4(c1a.x+c1b.x, c1a.y+c1b.y, c1a.z+c1b.z, c1a.w+c1b.w);
        const int cb = it*KTT + key0 + 2*tig;
        *(float2*)&sc[r0*SCP + cb    ] = make_float2(c0.x, c0.y);
        *(float2*)&sc[r1*SCP + cb    ] = make_float2(c0.z, c0.w);
        *(float2*)&sc[r0*SCP + cb + 8] = make_float2(c1.x, c1.y);
        *(float2*)&sc[r1*SCP + cb + 8] = make_float2(c1.z, c1.w);
    }

    // V0 into kv0 (all warps passed it=7's sync; kv0 last read at it=6)
    cp_tile(kv0, Vg, 0);
    __syncthreads();   // sc visible before cross-warp top-k reads

    // ====== exact top-k via bit-plane radix select + softmax ======
    {
        const int lane5 = t & 31;
        #pragma unroll 1
        for (int r = warp*2; r < warp*2 + 2; r++) {
            float* row = sc + r*SCP;
            unsigned u[32], tp[32];
            float mx = -3.4e38f;
            #pragma unroll
            for (int i = 0; i < 32; i++) {
                float f = row[i*32 + lane5];
                mx = fmaxf(mx, f);
                unsigned b = __float_as_uint(f);
                u[i] = b ^ (unsigned)(((int)b >> 31) | (int)0x80000000);
                tp[i] = u[i];
            }
            #pragma unroll
            for (int o = 16; o; o >>= 1) mx = fmaxf(mx, __shfl_xor_sync(0xffffffffu, mx, o));

            bit_transpose32(tp);

            unsigned active = 0xffffffffu, pref = 0;
            int kr = TOPK, asz = 1024;
            #pragma unroll
            for (int idx = 0; idx < 32; idx++) {
                unsigned s = active & tp[idx];
                int ctot = (int)__reduce_add_sync(0xffffffffu, (unsigned)__popc(s));
                if (ctot >= kr) { active = s; asz = ctot; pref |= (1u << (31 - idx)); }
                else            { kr -= ctot; active &= ~s; asz -= ctot; }
                if (asz == kr) break;
            }
            unsigned mn = 0xffffffffu;
            #pragma unroll
            for (int i = 0; i < 32; i++)
                if (u[i] >= pref) mn = min(mn, u[i]);
            mn = __reduce_min_sync(0xffffffffu, mn);

            float ssum = 0.f;
            #pragma unroll
            for (int i = 0; i < 32; i++) {
                float p = 0.f;
                if (u[i] >= mn) {
                    unsigned b = (u[i] & 0x80000000u) ? (u[i] ^ 0x80000000u) : ~u[i];
                    p = __expf(__uint_as_float(b) - mx);
                }
                ssum += p;
                row[i*32 + lane5] = __uint_as_float(f2tf(p));
            }
            #pragma unroll
            for (int o = 16; o; o >>= 1) ssum += __shfl_xor_sync(0xffffffffu, ssum, o);
            if (lane5 == 0) invs[r] = 1.f / ssum;
        }
    }

    // ======== PV (1xTF32, V pre-tf32), single-sync pipeline ========
    const int dc = (warp & 7) * 8;
    float4 oc[4];
    #pragma unroll
    for (int j = 0; j < 4; j++) oc[j] = make_float4(0.f,0.f,0.f,0.f);

    for (int it = 0; it < 8; it++) {
        cp_wait<0>();
        __syncthreads();
        if (it + 1 < 8) cp_tile((it & 1) ? kv0 : kv1, Vg, it + 1);
        const float* kb_ = (it & 1) ? kv1 : kv0;
        const int kb = it*KTT;
        #pragma unroll
        for (int ks = 0; ks < 16; ks++) {
            uint32_t Ap[4], Bv[2];
            Ap[0] = __float_as_uint(sc[r0*SCP + kb + ks*8 + tig    ]);
            Ap[1] = __float_as_uint(sc[r1*SCP + kb + ks*8 + tig    ]);
            Ap[2] = __float_as_uint(sc[r0*SCP + kb + ks*8 + tig + 4]);
            Ap[3] = __float_as_uint(sc[r1*SCP + kb + ks*8 + tig + 4]);
            Bv[0] = __float_as_uint(kb_[(ks*8 + tig    )*KVP + dc + gid]);
            Bv[1] = __float_as_uint(kb_[(ks*8 + tig + 4)*KVP + dc + gid]);
            mma_tf32(oc[ks >> 2], Ap, Bv);
        }
    }

    // epilogue
    {
        float4 o;
        o.x = (oc[0].x + oc[1].x) + (oc[2].x + oc[3].x);
        o.y = (oc[0].y + oc[1].y) + (oc[2].y + oc[3].y);
        o.z = (oc[0].z + oc[1].z) + (oc[2].z + oc[3].z);
        o.w = (oc[0].w + oc[1].w) + (oc[2].w + oc[3].w);
        const int bb = bh / Hh, hh = bh % Hh;
        const float iv0 = invs[r0], iv1 = invs[r1];
        const int d0 = dc + 2*tig;
        *(float2*)&g_AO[(size_t)((bb*Sq + q0 + r0)*Hh + hh)*Dd + d0] = make_float2(o.x*iv0, o.y*iv0);
        *(float2*)&g_AO[(size_t)((bb*Sq + q0 + r1)*Hh + hh)*Dd + d0] = make_float2(o.z*iv1, o.w*iv1);
    }
}

// ============================================================
// launch
// ============================================================
extern "C" void kernel_launch(void* const* d_in, const int* in_sizes, int n_in,
                              void* d_out, int out_size) {
    const float* hidden = (const float*)d_in[0];
    const float* Wqkv   = (const float*)d_in[1];
    const float* bqkv   = (const float*)d_in[2];
    const float* Wproj  = (const float*)d_in[3];
    const float* bproj  = (const float*)d_in[4];
    float* out = (float*)d_out;

    const int attn_smem = 53536 * (int)sizeof(float);  // 214144 B
    cudaFuncSetAttribute(attn_kernel, cudaFuncAttributeMaxDynamicSharedMemorySize, attn_smem);

    gemm_tf32<N3, true ><<<dim3(N3/128, (Bz*Sq)/128), 256>>>(hidden, Wqkv, bqkv, nullptr);
    attn_kernel<<<dim3(Sq/QT, Bz*Hh), 512, attn_smem>>>();
    gemm_tf32<Ed, false><<<dim3(Ed/128, (Bz*Sq)/128), 256>>>(nullptr, Wproj, bproj, out);
}

// round 17
// speedup vs baseline: 1.2610x; 1.0563x over previous
#include <cuda_runtime.h>
#include <cstdint>

#define Bz 8
#define Sq 1024
#define Ed 768
#define Hh 12
#define Dd 64
#define N3 2304
#define TOPK 409
#define QT 32
#define KTT 128
#define KVP 72     // V smem row stride (fp32 words)
#define KP0 36     // packed K plane row stride (uint32 words)
#define QBP 34     // packed q plane row stride
#define SCP 1028

#define ASTR 20
#define BSTR 136

// ---- scratch (allocation-free rule: __device__ globals) ----
__device__ float    g_Q [Bz*Hh*Sq*Dd];
__device__ uint32_t g_K0[Bz*Hh*Sq*(Dd/2)];   // K bf16x2 hi plane (packed pairs)
__device__ uint32_t g_K1[Bz*Hh*Sq*(Dd/2)];   // K bf16x2 residual plane
__device__ float    g_V [Bz*Hh*Sq*Dd];       // pre-rounded to tf32
__device__ float    g_AO[Bz*Sq*Ed];          // [b,s,h,d] = [8192, 768]

// ---- cp.async helpers ----
__device__ __forceinline__ void cp16(void* smem_dst, const void* gmem_src) {
    unsigned s = (unsigned)__cvta_generic_to_shared(smem_dst);
    asm volatile("cp.async.cg.shared.global [%0], [%1], 16;" :: "r"(s), "l"(gmem_src));
}
__device__ __forceinline__ void cp_commit() { asm volatile("cp.async.commit_group;"); }
template<int N>
__device__ __forceinline__ void cp_wait() { asm volatile("cp.async.wait_group %0;" :: "n"(N)); }

// ---- tf32 helpers ----
__device__ __forceinline__ uint32_t f2tf(float x) {
    uint32_t r; asm("cvt.rna.tf32.f32 %0, %1;" : "=r"(r) : "f"(x)); return r;
}
__device__ __forceinline__ void split_tf32(float x, uint32_t& hi, uint32_t& lo) {
    uint32_t h;
    asm("cvt.rna.tf32.f32 %0, %1;" : "=r"(h) : "f"(x));
    float l = x - __uint_as_float(h);
    uint32_t lw;
    asm("cvt.rna.tf32.f32 %0, %1;" : "=r"(lw) : "f"(l));
    hi = h; lo = lw;
}
__device__ __forceinline__ void mma_tf32(float4& d, const uint32_t a[4], const uint32_t b[2]) {
    asm volatile("mma.sync.aligned.m16n8k8.row.col.f32.tf32.tf32.f32 "
                 "{%0,%1,%2,%3}, {%4,%5,%6,%7}, {%8,%9}, {%0,%1,%2,%3};"
                 : "+f"(d.x), "+f"(d.y), "+f"(d.z), "+f"(d.w)
                 : "r"(a[0]), "r"(a[1]), "r"(a[2]), "r"(a[3]), "r"(b[0]), "r"(b[1]));
}

// ---- bf16x2 helpers ----
__device__ __forceinline__ uint32_t pack_bf16(float lo, float hi) {
    uint32_t r; asm("cvt.rn.bf16x2.f32 %0, %1, %2;" : "=r"(r) : "f"(hi), "f"(lo)); return r;
}
__device__ __forceinline__ float bf_lo(uint32_t p) { return __uint_as_float(p << 16); }
__device__ __forceinline__ float bf_hi(uint32_t p) { return __uint_as_float(p & 0xFFFF0000u); }
__device__ __forceinline__ void mma_bf16(float4& d, const uint32_t a[4], const uint32_t b[2]) {
    asm volatile("mma.sync.aligned.m16n8k16.row.col.f32.bf16.bf16.f32 "
                 "{%0,%1,%2,%3}, {%4,%5,%6,%7}, {%8,%9}, {%0,%1,%2,%3};"
                 : "+f"(d.x), "+f"(d.y), "+f"(d.z), "+f"(d.w)
                 : "r"(a[0]), "r"(a[1]), "r"(a[2]), "r"(a[3]), "r"(b[0]), "r"(b[1]));
}

// ---- 32x32 bit-matrix transpose (Hacker's Delight 7-7) ----
template<int J>
__device__ __forceinline__ void tstage(unsigned a[32], unsigned m) {
    #pragma unroll
    for (int g = 0; g < 16; g++) {
        const int k = ((g & ~(J - 1)) << 1) | (g & (J - 1));
        unsigned t = (a[k] ^ (a[k + J] >> J)) & m;
        a[k]     ^= t;
        a[k + J] ^= (t << J);
    }
}
__device__ __forceinline__ void bit_transpose32(unsigned a[32]) {
    tstage<16>(a, 0x0000FFFFu);
    tstage<8> (a, 0x00FF00FFu);
    tstage<4> (a, 0x0F0F0F0Fu);
    tstage<2> (a, 0x33333333u);
    tstage<1> (a, 0x55555555u);
}

// ============================================================
// 3xTF32 qkv GEMM. Epilogue: Q fp32, K packed bf16x2 planes,
// V pre-rounded tf32.
// ============================================================
__global__ __launch_bounds__(256, 2) void qkv_gemm(const float* __restrict__ A,
                                                   const float* __restrict__ W,
                                                   const float* __restrict__ bias) {
    __shared__ float As[2][128*ASTR];
    __shared__ float Bs[2][16*BSTR];

    const int t    = threadIdx.x;
    const int warp = t >> 5, lane = t & 31;
    const int gid  = lane >> 2, tig = lane & 3;
    const int m0   = blockIdx.y * 128, n0 = blockIdx.x * 128;
    const int wm   = (warp >> 2) * 64;
    const int wn   = (warp & 3) * 32;

    auto issue = [&](int buf, int kt) {
        #pragma unroll
        for (int i = 0; i < 2; i++) {
            int f = t + 256*i;
            int m = f >> 2, kc = (f & 3) << 2;
            cp16(&As[buf][m*ASTR + kc], &A[(size_t)(m0 + m)*Ed + kt*16 + kc]);
        }
        #pragma unroll
        for (int i = 0; i < 2; i++) {
            int f = t + 256*i;
            int kr = f >> 5, nc = (f & 31) << 2;
            cp16(&Bs[buf][kr*BSTR + nc], &W[(size_t)(kt*16 + kr)*N3 + n0 + nc]);
        }
        cp_commit();
    };

    float4 acc[4][4];
    #pragma unroll
    for (int i = 0; i < 4; i++)
        #pragma unroll
        for (int j = 0; j < 4; j++) acc[i][j] = make_float4(0.f, 0.f, 0.f, 0.f);

    issue(0, 0);
    const int NT = Ed / 16;
    for (int kt = 0; kt < NT; kt++) {
        cp_wait<0>();
        __syncthreads();
        if (kt + 1 < NT) issue((kt + 1) & 1, kt + 1);
        const float* as = As[kt & 1];
        const float* bs = Bs[kt & 1];
        #pragma unroll
        for (int ko = 0; ko < 16; ko += 8) {
            uint32_t Bhi[4][2], Blo[4][2];
            #pragma unroll
            for (int j = 0; j < 4; j++) {
                const int nc = wn + 8*j + gid;
                split_tf32(bs[(ko + tig    )*BSTR + nc], Bhi[j][0], Blo[j][0]);
                split_tf32(bs[(ko + tig + 4)*BSTR + nc], Bhi[j][1], Blo[j][1]);
            }
            #pragma unroll
            for (int i = 0; i < 4; i++) {
                const int r0 = wm + 16*i + gid;
                uint32_t Ahi[4], Alo[4];
                split_tf32(as[ r0     *ASTR + ko + tig    ], Ahi[0], Alo[0]);
                split_tf32(as[(r0 + 8)*ASTR + ko + tig    ], Ahi[1], Alo[1]);
                split_tf32(as[ r0     *ASTR + ko + tig + 4], Ahi[2], Alo[2]);
                split_tf32(as[(r0 + 8)*ASTR + ko + tig + 4], Ahi[3], Alo[3]);
                #pragma unroll
                for (int j = 0; j < 4; j++) {
                    mma_tf32(acc[i][j], Alo, Bhi[j]);
                    mma_tf32(acc[i][j], Ahi, Blo[j]);
                    mma_tf32(acc[i][j], Ahi, Bhi[j]);
                }
            }
        }
    }

    #pragma unroll
    for (int i = 0; i < 4; i++) {
        const int ma = m0 + wm + 16*i + gid;
        const int mb = ma + 8;
        #pragma unroll
        for (int j = 0; j < 4; j++) {
            const int nb = n0 + wn + 8*j + 2*tig;
            const float2 bv = *(const float2*)&bias[nb];
            float2 va = make_float2(acc[i][j].x + bv.x, acc[i][j].y + bv.y);
            float2 vb = make_float2(acc[i][j].z + bv.x, acc[i][j].w + bv.y);
            const int which = nb / Ed;
            const int hh    = (nb % Ed) >> 6;
            const int d0    = nb & 63;
            const int ba = ma >> 10, sa = ma & 1023;
            const int bbq = mb >> 10, sb = mb & 1023;
            if (which == 0) {
                *(float2*)&g_Q[(size_t)((ba*Hh + hh)*Sq + sa)*Dd + d0] = va;
                *(float2*)&g_Q[(size_t)((bbq*Hh + hh)*Sq + sb)*Dd + d0] = vb;
            } else if (which == 1) {
                // packed bf16x2 planes; word index = d0/2 (d0 even)
                const size_t wa = (size_t)((ba*Hh + hh)*Sq + sa)*(Dd/2) + (d0 >> 1);
                const size_t wb = (size_t)((bbq*Hh + hh)*Sq + sb)*(Dd/2) + (d0 >> 1);
                uint32_t h0 = pack_bf16(va.x, va.y);
                uint32_t h1 = pack_bf16(vb.x, vb.y);
                g_K0[wa] = h0;
                g_K1[wa] = pack_bf16(va.x - bf_lo(h0), va.y - bf_hi(h0));
                g_K0[wb] = h1;
                g_K1[wb] = pack_bf16(vb.x - bf_lo(h1), vb.y - bf_hi(h1));
            } else {
                float2 ta, tb;
                ta.x = __uint_as_float(f2tf(va.x)); ta.y = __uint_as_float(f2tf(va.y));
                tb.x = __uint_as_float(f2tf(vb.x)); tb.y = __uint_as_float(f2tf(vb.y));
                *(float2*)&g_V[(size_t)((ba*Hh + hh)*Sq + sa)*Dd + d0] = ta;
                *(float2*)&g_V[(size_t)((bbq*Hh + hh)*Sq + sb)*Dd + d0] = tb;
            }
        }
    }
}

// ============================================================
// bf16x2 EC proj GEMM: out = g_AO @ Wproj + bias (downstream
// of top-k -> no amplification; error ~1e-5).
// ============================================================
__global__ __launch_bounds__(256, 2) void proj_bf16(const float* __restrict__ W,
                                                    const float* __restrict__ bias,
                                                    float* __restrict__ out) {
    const float* A = (const float*)g_AO;   // device-side symbol!

    __shared__ float As[2][128*ASTR];
    __shared__ float Bs[2][16*BSTR];

    const int t    = threadIdx.x;
    const int warp = t >> 5, lane = t & 31;
    const int gid  = lane >> 2, tig = lane & 3;
    const int m0   = blockIdx.y * 128, n0 = blockIdx.x * 128;
    const int wm   = (warp >> 2) * 64;
    const int wn   = (warp & 3) * 32;

    auto issue = [&](int buf, int kt) {
        #pragma unroll
        for (int i = 0; i < 2; i++) {
            int f = t + 256*i;
            int m = f >> 2, kc = (f & 3) << 2;
            cp16(&As[buf][m*ASTR + kc], &A[(size_t)(m0 + m)*Ed + kt*16 + kc]);
        }
        #pragma unroll
        for (int i = 0; i < 2; i++) {
            int f = t + 256*i;
            int kr = f >> 5, nc = (f & 31) << 2;
            cp16(&Bs[buf][kr*BSTR + nc], &W[(size_t)(kt*16 + kr)*Ed + n0 + nc]);
        }
        cp_commit();
    };

    float4 acc[4][4];
    #pragma unroll
    for (int i = 0; i < 4; i++)
        #pragma unroll
        for (int j = 0; j < 4; j++) acc[i][j] = make_float4(0.f, 0.f, 0.f, 0.f);

    issue(0, 0);
    const int NT = Ed / 16;
    for (int kt = 0; kt < NT; kt++) {
        cp_wait<0>();
        __syncthreads();
        if (kt + 1 < NT) issue((kt + 1) & 1, kt + 1);
        const float* as = As[kt & 1];
        const float* bs = Bs[kt & 1];

        // one k16 step per tile
        uint32_t Bh[4][2], Bl[4][2];
        #pragma unroll
        for (int j = 0; j < 4; j++) {
            const int nc = wn + 8*j + gid;
            float b0 = bs[(2*tig    )*BSTR + nc], b1 = bs[(2*tig + 1)*BSTR + nc];
            float b8 = bs[(2*tig + 8)*BSTR + nc], b9 = bs[(2*tig + 9)*BSTR + nc];
            Bh[j][0] = pack_bf16(b0, b1);
            Bh[j][1] = pack_bf16(b8, b9);
            Bl[j][0] = pack_bf16(b0 - bf_lo(Bh[j][0]), b1 - bf_hi(Bh[j][0]));
            Bl[j][1] = pack_bf16(b8 - bf_lo(Bh[j][1]), b9 - bf_hi(Bh[j][1]));
        }
        #pragma unroll
        for (int i = 0; i < 4; i++) {
            const int r0 = wm + 16*i + gid;
            float2 a01  = *(const float2*)&as[ r0     *ASTR + 2*tig    ];
            float2 a01b = *(const float2*)&as[(r0 + 8)*ASTR + 2*tig    ];
            float2 a89  = *(const float2*)&as[ r0     *ASTR + 2*tig + 8];
            float2 a89b = *(const float2*)&as[(r0 + 8)*ASTR + 2*tig + 8];
            uint32_t Ah[4], Al[4];
            Ah[0] = pack_bf16(a01.x,  a01.y);
            Ah[1] = pack_bf16(a01b.x, a01b.y);
            Ah[2] = pack_bf16(a89.x,  a89.y);
            Ah[3] = pack_bf16(a89b.x, a89b.y);
            Al[0] = pack_bf16(a01.x  - bf_lo(Ah[0]), a01.y  - bf_hi(Ah[0]));
            Al[1] = pack_bf16(a01b.x - bf_lo(Ah[1]), a01b.y - bf_hi(Ah[1]));
            Al[2] = pack_bf16(a89.x  - bf_lo(Ah[2]), a89.y  - bf_hi(Ah[2]));
            Al[3] = pack_bf16(a89b.x - bf_lo(Ah[3]), a89b.y - bf_hi(Ah[3]));
            #pragma unroll
            for (int j = 0; j < 4; j++) {
                mma_bf16(acc[i][j], Al, Bh[j]);
                mma_bf16(acc[i][j], Ah, Bl[j]);
                mma_bf16(acc[i][j], Ah, Bh[j]);
            }
        }
    }

    #pragma unroll
    for (int i = 0; i < 4; i++) {
        const int ma = m0 + wm + 16*i + gid;
        const int mb = ma + 8;
        #pragma unroll
        for (int j = 0; j < 4; j++) {
            const int nb = n0 + wn + 8*j + 2*tig;
            const float2 bv = *(const float2*)&bias[nb];
            *(float2*)&out[(size_t)ma * Ed + nb] =
                make_float2(acc[i][j].x + bv.x, acc[i][j].y + bv.y);
            *(float2*)&out[(size_t)mb * Ed + nb] =
                make_float2(acc[i][j].z + bv.x, acc[i][j].w + bv.y);
        }
    }
}

// ============================================================
// Fused attention: bf16x2 scores from PRE-PACKED K planes
// (pure LDS+MMA), exact radix top-k, 1xTF32 PV.
// 512 thr, 1 CTA/SM, single-sync pipelines.
// ============================================================
__global__ __launch_bounds__(512, 1) void attn_kernel() {
    extern __shared__ float sm[];
    uint32_t* q_b0 = (uint32_t*)sm;          // 32*34 = 1088
    uint32_t* q_b1 = (uint32_t*)(sm + 1088); // 1088
    float* sc   = sm + 2176;                 // 32*1028 = 32896
    float* kv0  = sm + 35072;                // 9216 (K: 2 planes x 128 x 36 | V: 128 x 72)
    float* kv1  = sm + 44288;                // 9216
    float* invs = sm + 53504;                // 32
    // total 53536 floats = 214144 B

    const int t    = threadIdx.x;
    const int warp = t >> 5, lane = t & 31;
    const int gid  = lane >> 2, tig = lane & 3;
    const int bh = blockIdx.y;
    const int q0 = blockIdx.x * QT;
    const float*    Qg  = g_Q  + (size_t)bh*Sq*Dd;
    const uint32_t* K0g = g_K0 + (size_t)bh*Sq*(Dd/2);
    const uint32_t* K1g = g_K1 + (size_t)bh*Sq*(Dd/2);
    const float*    Vg  = g_V  + (size_t)bh*Sq*Dd;

    auto cp_ktile = [&](float* buf, int kt0) {
        uint32_t* b32 = (uint32_t*)buf;
        #pragma unroll
        for (int i = 0; i < 2; i++) {       // plane 0: 1024 f4 (4096 words)
            int idx = t + 512*i;
            int row = idx >> 3, w4 = (idx & 7) << 2;
            cp16(&b32[row*KP0 + w4], &K0g[(size_t)(kt0*KTT + row)*(Dd/2) + w4]);
        }
        #pragma unroll
        for (int i = 0; i < 2; i++) {       // plane 1
            int idx = t + 512*i;
            int row = idx >> 3, w4 = (idx & 7) << 2;
            cp16(&b32[4608 + row*KP0 + w4], &K1g[(size_t)(kt0*KTT + row)*(Dd/2) + w4]);
        }
        cp_commit();
    };
    auto cp_vtile = [&](float* buf, int kt0) {
        #pragma unroll
        for (int i = 0; i < 4; i++) {
            int f = t + 512*i;
            int row = f >> 4, c4 = (f & 15) << 2;
            cp16(&buf[row*KVP + c4], &Vg[(size_t)(kt0*KTT + row)*Dd + c4]);
        }
        cp_commit();
    };

    cp_ktile(kv0, 0);
    // stage q: scale 0.125, split to bf16 hi + residual, packed
    {
        const int prow = t >> 4, pc4 = (t & 15) << 2;
        float4 v = *(const float4*)&Qg[(size_t)(q0 + prow)*Dd + pc4];
        v.x *= 0.125f; v.y *= 0.125f; v.z *= 0.125f; v.w *= 0.125f;
        uint32_t p0a = pack_bf16(v.x, v.y);
        uint32_t p0b = pack_bf16(v.z, v.w);
        uint32_t p1a = pack_bf16(v.x - bf_lo(p0a), v.y - bf_hi(p0a));
        uint32_t p1b = pack_bf16(v.z - bf_lo(p0b), v.w - bf_hi(p0b));
        const int w = pc4 >> 1;
        q_b0[prow*QBP + w]     = p0a;  q_b0[prow*QBP + w + 1] = p0b;
        q_b1[prow*QBP + w]     = p1a;  q_b1[prow*QBP + w + 1] = p1b;
    }
    __syncthreads();

    const int qh_  = warp >> 3;
    const int key0 = (warp & 7) * 16;
    const int r0 = qh_*16 + gid, r1 = r0 + 8;

    uint32_t qa0[4][4], qa1[4][4];
    #pragma unroll
    for (int s = 0; s < 4; s++) {
        qa0[s][0] = q_b0[r0*QBP + s*8 + tig    ];
        qa0[s][1] = q_b0[r1*QBP + s*8 + tig    ];
        qa0[s][2] = q_b0[r0*QBP + s*8 + tig + 4];
        qa0[s][3] = q_b0[r1*QBP + s*8 + tig + 4];
        qa1[s][0] = q_b1[r0*QBP + s*8 + tig    ];
        qa1[s][1] = q_b1[r1*QBP + s*8 + tig    ];
        qa1[s][2] = q_b1[r0*QBP + s*8 + tig + 4];
        qa1[s][3] = q_b1[r1*QBP + s*8 + tig + 4];
    }

    // ======== scores (bf16x2 from packed planes: pure LDS+MMA) ========
    for (int it = 0; it < 8; it++) {
        cp_wait<0>();
        __syncthreads();
        if (it + 1 < 8) cp_ktile((it & 1) ? kv0 : kv1, it + 1);
        const uint32_t* K0s = (const uint32_t*)((it & 1) ? kv1 : kv0);
        const uint32_t* K1s = K0s + 4608;

        float4 c0a = make_float4(0.f,0.f,0.f,0.f), c0b = c0a, c1a = c0a, c1b = c0a;
        #pragma unroll
        for (int s = 0; s < 4; s++) {
            {
                const int key = key0 + gid;
                uint32_t b0[2], b1[2];
                b0[0] = K0s[key*KP0 + s*8 + tig];  b0[1] = K0s[key*KP0 + s*8 + tig + 4];
                b1[0] = K1s[key*KP0 + s*8 + tig];  b1[1] = K1s[key*KP0 + s*8 + tig + 4];
                float4& c = (s & 1) ? c0b : c0a;
                mma_bf16(c, qa1[s], b0); mma_bf16(c, qa0[s], b1); mma_bf16(c, qa0[s], b0);
            }
            {
                const int key = key0 + 8 + gid;
                uint32_t b0[2], b1[2];
                b0[0] = K0s[key*KP0 + s*8 + tig];  b0[1] = K0s[key*KP0 + s*8 + tig + 4];
                b1[0] = K1s[key*KP0 + s*8 + tig];  b1[1] = K1s[key*KP0 + s*8 + tig + 4];
                float4& c = (s & 1) ? c1b : c1a;
                mma_bf16(c, qa1[s], b0); mma_bf16(c, qa0[s], b1); mma_bf16(c, qa0[s], b0);
            }
        }
        float4 c0 = make_float4(c0a.x+c0b.x, c0a.y+c0b.y, c0a.z+c0b.z, c0a.w+c0b.w);
        float4 c1 = make_float4(c1a.x+c1b.x, c1a.y+c1b.y, c1a.z+c1b.z, c1a.w+c1b.w);
        const int cb = it*KTT + key0 + 2*tig;
        *(float2*)&sc[r0*SCP + cb    ] = make_float2(c0.x, c0.y);
        *(float2*)&sc[r1*SCP + cb    ] = make_float2(c0.z, c0.w);
        *(float2*)&sc[r0*SCP + cb + 8] = make_float2(c1.x, c1.y);
        *(float2*)&sc[r1*SCP + cb + 8] = make_float2(c1.z, c1.w);
    }

    cp_vtile(kv0, 0);
    __syncthreads();   // sc visible before cross-warp top-k reads

    // ====== exact top-k via bit-plane radix select + softmax ======
    {
        const int lane5 = t & 31;
        #pragma unroll 1
        for (int r = warp*2; r < warp*2 + 2; r++) {
            float* row = sc + r*SCP;
            unsigned u[32], tp[32];
            float mx = -3.4e38f;
            #pragma unroll
            for (int i = 0; i < 32; i++) {
                float f = row[i*32 + lane5];
                mx = fmaxf(mx, f);
                unsigned b = __float_as_uint(f);
                u[i] = b ^ (unsigned)(((int)b >> 31) | (int)0x80000000);
                tp[i] = u[i];
            }
            #pragma unroll
            for (int o = 16; o; o >>= 1) mx = fmaxf(mx, __shfl_xor_sync(0xffffffffu, mx, o));

            bit_transpose32(tp);

            unsigned active = 0xffffffffu, pref = 0;
            int kr = TOPK, asz = 1024;
            #pragma unroll
            for (int idx = 0; idx < 32; idx++) {
                unsigned s = active & tp[idx];
                int ctot = (int)__reduce_add_sync(0xffffffffu, (unsigned)__popc(s));
                if (ctot >= kr) { active = s; asz = ctot; pref |= (1u << (31 - idx)); }
                else            { kr -= ctot; active &= ~s; asz -= ctot; }
                if (asz == kr) break;
            }
            unsigned mn = 0xffffffffu;
            #pragma unroll
            for (int i = 0; i < 32; i++)
                if (u[i] >= pref) mn = min(mn, u[i]);
            mn = __reduce_min_sync(0xffffffffu, mn);

            float ssum = 0.f;
            #pragma unroll
            for (int i = 0; i < 32; i++) {
                float p = 0.f;
                if (u[i] >= mn) {
                    unsigned b = (u[i] & 0x80000000u) ? (u[i] ^ 0x80000000u) : ~u[i];
                    p = __expf(__uint_as_float(b) - mx);
                }
                ssum += p;
                row[i*32 + lane5] = __uint_as_float(f2tf(p));
            }
            #pragma unroll
            for (int o = 16; o; o >>= 1) ssum += __shfl_xor_sync(0xffffffffu, ssum, o);
            if (lane5 == 0) invs[r] = 1.f / ssum;
        }
    }

    // ======== PV (1xTF32, V pre-tf32), single-sync pipeline ========
    const int dc = (warp & 7) * 8;
    float4 oc[4];
    #pragma unroll
    for (int j = 0; j < 4; j++) oc[j] = make_float4(0.f,0.f,0.f,0.f);

    for (int it = 0; it < 8; it++) {
        cp_wait<0>();
        __syncthreads();
        if (it + 1 < 8) cp_vtile((it & 1) ? kv0 : kv1, it + 1);
        const float* kb_ = (it & 1) ? kv1 : kv0;
        const int kb = it*KTT;
        #pragma unroll
        for (int ks = 0; ks < 16; ks++) {
            uint32_t Ap[4], Bv[2];
            Ap[0] = __float_as_uint(sc[r0*SCP + kb + ks*8 + tig    ]);
            Ap[1] = __float_as_uint(sc[r1*SCP + kb + ks*8 + tig    ]);
            Ap[2] = __float_as_uint(sc[r0*SCP + kb + ks*8 + tig + 4]);
            Ap[3] = __float_as_uint(sc[r1*SCP + kb + ks*8 + tig + 4]);
            Bv[0] = __float_as_uint(kb_[(ks*8 + tig    )*KVP + dc + gid]);
            Bv[1] = __float_as_uint(kb_[(ks*8 + tig + 4)*KVP + dc + gid]);
            mma_tf32(oc[ks >> 2], Ap, Bv);
        }
    }

    // epilogue
    {
        float4 o;
        o.x = (oc[0].x + oc[1].x) + (oc[2].x + oc[3].x);
        o.y = (oc[0].y + oc[1].y) + (oc[2].y + oc[3].y);
        o.z = (oc[0].z + oc[1].z) + (oc[2].z + oc[3].z);
        o.w = (oc[0].w + oc[1].w) + (oc[2].w + oc[3].w);
        const int bb = bh / Hh, hh = bh % Hh;
        const float iv0 = invs[r0], iv1 = invs[r1];
        const int d0 = dc + 2*tig;
        *(float2*)&g_AO[(size_t)((bb*Sq + q0 + r0)*Hh + hh)*Dd + d0] = make_float2(o.x*iv0, o.y*iv0);
        *(float2*)&g_AO[(size_t)((bb*Sq + q0 + r1)*Hh + hh)*Dd + d0] = make_float2(o.z*iv1, o.w*iv1);
    }
}

// ============================================================
// launch
// ============================================================
extern "C" void kernel_launch(void* const* d_in, const int* in_sizes, int n_in,
                              void* d_out, int out_size) {
    const float* hidden = (const float*)d_in[0];
    const float* Wqkv   = (const float*)d_in[1];
    const float* bqkv   = (const float*)d_in[2];
    const float* Wproj  = (const float*)d_in[3];
    const float* bproj  = (const float*)d_in[4];
    float* out = (float*)d_out;

    const int attn_smem = 53536 * (int)sizeof(float);  // 214144 B
    cudaFuncSetAttribute(attn_kernel, cudaFuncAttributeMaxDynamicSharedMemorySize, attn_smem);

    qkv_gemm<<<dim3(N3/128, (Bz*Sq)/128), 256>>>(hidden, Wqkv, bqkv);
    attn_kernel<<<dim3(Sq/QT, Bz*Hh), 512, attn_smem>>>();
    proj_bf16<<<dim3(Ed/128, (Bz*Sq)/128), 256>>>(Wproj, bproj, out);
}